// round 12
// baseline (speedup 1.0000x reference)
#include <cuda_runtime.h>
#include <cuda_bf16.h>
#include <math.h>

// Shapes fixed for this bench: B=4, H=8, N=512, DK=64
#define BB 4
#define HH 8
#define NN 512
#define DKK 64
#define TI 8                 // i-rows per CTA
#define NT 512               // threads per CTA (16 warps)
#define SCALE 0.125f         // 1/sqrt(64)
#define SROW 516             // padded score row (stride mod 32 = 4)
#define TIBLK (HH*SROW + 4)  // 4132 (stride mod 32 = 4)

// smem layout in floats
#define S_OFF    0
#define RED1_OFF (TI*TIBLK)                    // 33056 ; [2][TI*HH][DKK] p.v
#define RED2_OFF (RED1_OFF + 2*TI*HH*DKK)      // 41248 ; [TI*HH][DKK]  p.rel
#define LP_OFF   (RED2_OFF + TI*HH*DKK)        // 45344 ; [TI*HH] row sums
#define SMEM_FLOATS (LP_OFF + TI*HH)           // 45408
#define SMEM_BYTES (SMEM_FLOATS * 4)           // 181632 (< 227 KB)

// ---------------- packed f32x2 helpers (FFMA2 on sm_103a) ----------------
__device__ __forceinline__ unsigned long long f2u(float2 a) {
    unsigned long long r;
    asm("mov.b64 %0, {%1, %2};" : "=l"(r) : "f"(a.x), "f"(a.y));
    return r;
}
__device__ __forceinline__ float2 u2f(unsigned long long a) {
    float2 r;
    asm("mov.b64 {%0, %1}, %2;" : "=f"(r.x), "=f"(r.y) : "l"(a));
    return r;
}
__device__ __forceinline__ float2 ffma2(float2 a, float2 b, float2 c) {
    unsigned long long r;
    asm("fma.rn.f32x2 %0, %1, %2, %3;"
        : "=l"(r) : "l"(f2u(a)), "l"(f2u(b)), "l"(f2u(c)));
    return u2f(r);
}
__device__ __forceinline__ float2 lo2(float4 v) { return make_float2(v.x, v.y); }
__device__ __forceinline__ float2 hi2(float4 v) { return make_float2(v.z, v.w); }

// Reduce 8 per-lane values r[0..7] across the 8 dd-lanes; lane dd -> sum of r[dd].
__device__ __forceinline__ float butterfly8(const float r[8],
                                            bool b0, bool b1, bool b2) {
    float c0 = b2 ? r[4] : r[0];
    float c1 = b2 ? r[5] : r[1];
    float c2 = b2 ? r[6] : r[2];
    float c3 = b2 ? r[7] : r[3];
    float d0 = b2 ? r[0] : r[4];
    float d1 = b2 ? r[1] : r[5];
    float d2 = b2 ? r[2] : r[6];
    float d3 = b2 ? r[3] : r[7];
    c0 += __shfl_xor_sync(0xffffffffu, d0, 4);
    c1 += __shfl_xor_sync(0xffffffffu, d1, 4);
    c2 += __shfl_xor_sync(0xffffffffu, d2, 4);
    c3 += __shfl_xor_sync(0xffffffffu, d3, 4);
    float e0 = b1 ? c2 : c0;
    float e1 = b1 ? c3 : c1;
    float f0 = b1 ? c0 : c2;
    float f1 = b1 ? c1 : c3;
    e0 += __shfl_xor_sync(0xffffffffu, f0, 2);
    e1 += __shfl_xor_sync(0xffffffffu, f1, 2);
    float w = b0 ? e1 : e0;
    float o = b0 ? e0 : e1;
    w += __shfl_xor_sync(0xffffffffu, o, 1);
    return w;
}

// Reduce 4 per-lane values r[0..3] across 8 dd-lanes; EVERY lane ends with the
// full sum of r[dd&3]. (xor2, xor1 reduce within half; xor4 folds halves.)
__device__ __forceinline__ float butterfly4(const float r[4],
                                            bool b0, bool b1) {
    float k0 = b1 ? r[2] : r[0];
    float k1 = b1 ? r[3] : r[1];
    float o0 = b1 ? r[0] : r[2];
    float o1 = b1 ? r[1] : r[3];
    k0 += __shfl_xor_sync(0xffffffffu, o0, 2);
    k1 += __shfl_xor_sync(0xffffffffu, o1, 2);
    float kk = b0 ? k1 : k0;
    float oo = b0 ? k0 : k1;
    kk += __shfl_xor_sync(0xffffffffu, oo, 1);
    kk += __shfl_xor_sync(0xffffffffu, kk, 4);
    return kk;
}

__global__ __launch_bounds__(NT, 1)
void rel_attn_kernel(const float* __restrict__ q,
                     const float* __restrict__ k,
                     const float* __restrict__ v,
                     const float* __restrict__ rel,
                     const float* __restrict__ mask,
                     float* __restrict__ out) {
    extern __shared__ float sm[];
    float* s_s   = sm + S_OFF;     // [TI]{[HH][SROW]} content scores -> e
    float* red1  = sm + RED1_OFF;  // [2][TI*HH][DKK] p.v per-jhalf partials
    float* red2  = sm + RED2_OFF;  // [TI*HH][DKK]    p.rel full sums
    float* lpart = sm + LP_OFF;    // [TI*HH] row sums

    const int bid  = blockIdx.x;
    const int b    = bid >> 6;
    const int i0   = (bid & 63) * TI;
    const int tid  = threadIdx.x;
    const int warp = tid >> 5;
    const int lane = tid & 31;
    const int dd   = lane & 7;
    const int jj   = lane >> 3;
    const bool b0  = (dd & 1) != 0;
    const bool b1  = (dd & 2) != 0;
    const bool b2  = (dd & 4) != 0;

    const float2 z2 = make_float2(0.f, 0.f);

    // ===== Phase 1a: content scores s = (scale*q).k ; warp=(h, jhalf) =======
    {
        const int h  = warp & 7;
        const int jo = (warp >> 3) * (NN / 2);
        float4 qa[TI], qb[TI];
#pragma unroll
        for (int ti = 0; ti < TI; ti++) {
            const float* qp = q + ((size_t)(b * HH + h) * NN + (i0 + ti)) * DKK + dd * 8;
            float4 a = *(const float4*)qp;
            float4 c = *(const float4*)(qp + 4);
            a.x *= SCALE; a.y *= SCALE; a.z *= SCALE; a.w *= SCALE;
            c.x *= SCALE; c.y *= SCALE; c.z *= SCALE; c.w *= SCALE;
            qa[ti] = a; qb[ti] = c;
        }
        const float* kbase = k + ((size_t)(b * HH + h) * NN) * DKK + dd * 8;
        float4 ka = *(const float4*)(kbase + (size_t)(jo + jj) * DKK);
        float4 kb = *(const float4*)(kbase + (size_t)(jo + jj) * DKK + 4);
#pragma unroll 2
        for (int s = 0; s < NN / 8; s++) {
            const int j  = jo + s * 4 + jj;
            const int sn = (s < NN / 8 - 1) ? s + 1 : s;
            const int jn = jo + sn * 4 + jj;
            const float4 na = *(const float4*)(kbase + (size_t)jn * DKK);
            const float4 nb = *(const float4*)(kbase + (size_t)jn * DKK + 4);
            float r[TI];
#pragma unroll
            for (int ti = 0; ti < TI; ti++) {
                float2 a = ffma2(lo2(qa[ti]), lo2(ka), z2);
                a = ffma2(hi2(qa[ti]), hi2(ka), a);
                a = ffma2(lo2(qb[ti]), lo2(kb), a);
                a = ffma2(hi2(qb[ti]), hi2(kb), a);
                r[ti] = a.x + a.y;
            }
            const float w = butterfly8(r, b0, b1, b2);   // lane dd -> ti=dd
            s_s[dd * TIBLK + h * SROW + j] = w;          // conflict-free
            ka = na; kb = nb;
        }
    }
    __syncthreads();

    // ===== FUSED phase: rel scores + exp + p.rel accumulate =================
    // warp = (ti, hg): heads hg*4..hg*4+3, ALL j. rel loaded ONCE from DRAM
    // (the two hg warps of a ti share lines via L1 pending-miss merge).
    {
        const int ti = warp & 7;
        const int hg = warp >> 3;          // head group (0: h0-3, 1: h4-7)
        const int hl = dd & 3;             // this lane's head within group
        const int h  = hg * 4 + hl;

        float4 qa[4], qb[4];
#pragma unroll
        for (int t = 0; t < 4; t++) {
            const float* qp = q + ((size_t)(b * HH + hg * 4 + t) * NN + (i0 + ti)) * DKK + dd * 8;
            qa[t] = *(const float4*)qp;
            qb[t] = *(const float4*)(qp + 4);
        }
        float2 acc[4][4];
#pragma unroll
        for (int t = 0; t < 4; t++)
#pragma unroll
            for (int c = 0; c < 4; c++) acc[t][c] = z2;
        float lsum = 0.f;

        const float* rbase = rel + (((size_t)b * NN + (i0 + ti)) * NN) * DKK + dd * 8;
        const float* mrow  = mask + ((size_t)(b * HH + h) * NN + (i0 + ti)) * NN;
        float* srow = s_s + ti * TIBLK + h * SROW;

        float4 ra = __ldg((const float4*)(rbase + (size_t)jj * DKK));
        float4 rb = __ldg((const float4*)(rbase + (size_t)jj * DKK + 4));
#pragma unroll 2
        for (int s = 0; s < NN / 4; s++) {
            const int j  = s * 4 + jj;
            const int sn = (s < NN / 4 - 1) ? s + 1 : s;
            const int jn = sn * 4 + jj;
            const float4 na = __ldg((const float4*)(rbase + (size_t)jn * DKK));
            const float4 nb = __ldg((const float4*)(rbase + (size_t)jn * DKK + 4));
            const float mval = mrow[j];
            const float cval = srow[j];                   // content score (LDS)
            float r[4];
#pragma unroll
            for (int t = 0; t < 4; t++) {
                float2 a = ffma2(lo2(qa[t]), lo2(ra), z2);
                a = ffma2(hi2(qa[t]), hi2(ra), a);
                a = ffma2(lo2(qb[t]), lo2(rb), a);
                a = ffma2(hi2(qb[t]), hi2(rb), a);
                r[t] = a.x + a.y;
            }
            const float w = butterfly4(r, b0, b1);        // all lanes: score(h=hl)
            const float e = __expf(w + cval + mval);
            if (dd < 4) srow[j] = e;                      // store p for phase 2a
            lsum += e;
            // allgather the 4 head e's across hl lanes (3 shfls)
            const float r1 = __shfl_xor_sync(0xffffffffu, e, 1);
            const float e0 = b0 ? r1 : e;
            const float e1 = b0 ? e : r1;
            const float f0 = __shfl_xor_sync(0xffffffffu, e0, 2);
            const float f1 = __shfl_xor_sync(0xffffffffu, e1, 2);
            const float g0 = b1 ? f0 : e0;
            const float g1 = b1 ? f1 : e1;
            const float g2 = b1 ? e0 : f0;
            const float g3 = b1 ? e1 : f1;
            const float2 p0 = make_float2(g0, g0);
            const float2 p1 = make_float2(g1, g1);
            const float2 p2 = make_float2(g2, g2);
            const float2 p3 = make_float2(g3, g3);
            acc[0][0] = ffma2(p0, lo2(ra), acc[0][0]);
            acc[0][1] = ffma2(p0, hi2(ra), acc[0][1]);
            acc[0][2] = ffma2(p0, lo2(rb), acc[0][2]);
            acc[0][3] = ffma2(p0, hi2(rb), acc[0][3]);
            acc[1][0] = ffma2(p1, lo2(ra), acc[1][0]);
            acc[1][1] = ffma2(p1, hi2(ra), acc[1][1]);
            acc[1][2] = ffma2(p1, lo2(rb), acc[1][2]);
            acc[1][3] = ffma2(p1, hi2(rb), acc[1][3]);
            acc[2][0] = ffma2(p2, lo2(ra), acc[2][0]);
            acc[2][1] = ffma2(p2, hi2(ra), acc[2][1]);
            acc[2][2] = ffma2(p2, lo2(rb), acc[2][2]);
            acc[2][3] = ffma2(p2, hi2(rb), acc[2][3]);
            acc[3][0] = ffma2(p3, lo2(ra), acc[3][0]);
            acc[3][1] = ffma2(p3, hi2(ra), acc[3][1]);
            acc[3][2] = ffma2(p3, lo2(rb), acc[3][2]);
            acc[3][3] = ffma2(p3, hi2(rb), acc[3][3]);
            ra = na; rb = nb;
        }

        // row sums: lanes dd and dd^4 hold IDENTICAL partial sums (same hl,
        // same jj), so reduce ONLY over the jj bits (xor 8, 16). Lane<4 then
        // holds the full row sum for head hg*4+hl.
        lsum += __shfl_xor_sync(0xffffffffu, lsum, 8);
        lsum += __shfl_xor_sync(0xffffffffu, lsum, 16);
        if (lane < 4) lpart[ti * HH + hg * 4 + hl] = lsum;

        // reduce acc over jj groups, write p.rel sums
#pragma unroll
        for (int t = 0; t < 4; t++)
#pragma unroll
            for (int c = 0; c < 4; c++) {
                acc[t][c].x += __shfl_xor_sync(0xffffffffu, acc[t][c].x, 8);
                acc[t][c].x += __shfl_xor_sync(0xffffffffu, acc[t][c].x, 16);
                acc[t][c].y += __shfl_xor_sync(0xffffffffu, acc[t][c].y, 8);
                acc[t][c].y += __shfl_xor_sync(0xffffffffu, acc[t][c].y, 16);
            }
        if (jj == 0) {
#pragma unroll
            for (int t = 0; t < 4; t++) {
                float* rp = red2 + (ti * HH + hg * 4 + t) * DKK + dd * 8;
                *(float4*)rp       = make_float4(acc[t][0].x, acc[t][0].y,
                                                 acc[t][1].x, acc[t][1].y);
                *(float4*)(rp + 4) = make_float4(acc[t][2].x, acc[t][2].y,
                                                 acc[t][3].x, acc[t][3].y);
            }
        }
    }
    __syncthreads();

    // ===== Phase 2a: out1 = p.v ; warp=(h, jhalf) ===========================
    {
        const int h  = warp & 7;
        const int jh = warp >> 3;
        const int jo = jh * (NN / 2);
        float2 acc[TI][4];
#pragma unroll
        for (int ti = 0; ti < TI; ti++)
#pragma unroll
            for (int c = 0; c < 4; c++) acc[ti][c] = z2;

        const float* vbase = v + ((size_t)(b * HH + h) * NN) * DKK + dd * 8;
        float4 va = *(const float4*)(vbase + (size_t)(jo + jj) * DKK);
        float4 vb = *(const float4*)(vbase + (size_t)(jo + jj) * DKK + 4);
#pragma unroll 2
        for (int s = 0; s < NN / 8; s++) {
            const int j  = jo + s * 4 + jj;
            const int sn = (s < NN / 8 - 1) ? s + 1 : s;
            const int jn = jo + sn * 4 + jj;
            const float4 na = *(const float4*)(vbase + (size_t)jn * DKK);
            const float4 nb = *(const float4*)(vbase + (size_t)jn * DKK + 4);
#pragma unroll
            for (int ti = 0; ti < TI; ti++) {
                const float e = s_s[ti * TIBLK + h * SROW + j];
                const float2 e2 = make_float2(e, e);
                acc[ti][0] = ffma2(e2, lo2(va), acc[ti][0]);
                acc[ti][1] = ffma2(e2, hi2(va), acc[ti][1]);
                acc[ti][2] = ffma2(e2, lo2(vb), acc[ti][2]);
                acc[ti][3] = ffma2(e2, hi2(vb), acc[ti][3]);
            }
            va = na; vb = nb;
        }
#pragma unroll
        for (int ti = 0; ti < TI; ti++)
#pragma unroll
            for (int c = 0; c < 4; c++) {
                acc[ti][c].x += __shfl_xor_sync(0xffffffffu, acc[ti][c].x, 8);
                acc[ti][c].x += __shfl_xor_sync(0xffffffffu, acc[ti][c].x, 16);
                acc[ti][c].y += __shfl_xor_sync(0xffffffffu, acc[ti][c].y, 8);
                acc[ti][c].y += __shfl_xor_sync(0xffffffffu, acc[ti][c].y, 16);
            }
        if (jj == 0) {
#pragma unroll
            for (int ti = 0; ti < TI; ti++) {
                float* rp = red1 + ((size_t)jh * TI * HH * DKK) +
                            (ti * HH + h) * DKK + dd * 8;
                *(float4*)rp       = make_float4(acc[ti][0].x, acc[ti][0].y,
                                                 acc[ti][1].x, acc[ti][1].y);
                *(float4*)(rp + 4) = make_float4(acc[ti][2].x, acc[ti][2].y,
                                                 acc[ti][3].x, acc[ti][3].y);
            }
        }
    }
    __syncthreads();

    // ===== Combine + normalize + store (float4) =============================
    {
        const int Q = TI * HH * DKK / 4;            // 1024 float4s
        const float4* r14 = (const float4*)red1;
        const float4* r24 = (const float4*)red2;
#pragma unroll
        for (int it = 0; it < 2; it++) {
            const int idx4 = it * NT + tid;
            const float4 a0 = r14[idx4];
            const float4 a1 = r14[Q + idx4];
            const float4 c0 = r24[idx4];
            const int row = idx4 >> 4;               // ti*8+h
            const int ti  = row >> 3;
            const int h   = row & 7;
            const int d   = (idx4 & 15) << 2;
            const float s = 1.0f / lpart[row];
            float4 o;
            o.x = ((a0.x + a1.x) + c0.x) * s;
            o.y = ((a0.y + a1.y) + c0.y) * s;
            o.z = ((a0.z + a1.z) + c0.z) * s;
            o.w = ((a0.w + a1.w) + c0.w) * s;
            *(float4*)&out[((size_t)(b * HH + h) * NN + (i0 + ti)) * DKK + d] = o;
        }
    }
}

extern "C" void kernel_launch(void* const* d_in, const int* in_sizes, int n_in,
                              void* d_out, int out_size) {
    const float* q    = (const float*)d_in[0];
    const float* k    = (const float*)d_in[1];
    const float* v    = (const float*)d_in[2];
    const float* rel  = (const float*)d_in[3];
    const float* mask = (const float*)d_in[4];
    float* out = (float*)d_out;

    cudaFuncSetAttribute(rel_attn_kernel,
                         cudaFuncAttributeMaxDynamicSharedMemorySize, SMEM_BYTES);
    rel_attn_kernel<<<BB * (NN / TI), NT, SMEM_BYTES>>>(q, k, v, rel, mask, out);
}

// round 13
// speedup vs baseline: 1.0305x; 1.0305x over previous
#include <cuda_runtime.h>
#include <cuda_bf16.h>
#include <math.h>

// Shapes fixed for this bench: B=4, H=8, N=512, DK=64
#define BB 4
#define HH 8
#define NN 512
#define DKK 64
#define TI 8                 // i-rows per CTA
#define NT 512               // threads per CTA (16 warps)
#define SCALE 0.125f         // 1/sqrt(64)
#define SROW 516             // padded score row (stride mod 32 = 4)
#define TIBLK (HH*SROW + 4)  // 4132 (stride mod 32 = 4)
#define JCH 128              // j-chunk (rel reload stays L2/L1-hot)

// smem layout in floats
#define S_OFF    0
#define RED1_OFF (TI*TIBLK)                    // 33056 ; [2][TI*HH][DKK] p.v
#define RED2_OFF (RED1_OFF + 2*TI*HH*DKK)      // 41248 ; [TI*HH][DKK]  p.rel
#define LP_OFF   (RED2_OFF + TI*HH*DKK)        // 45344 ; [TI*HH] row sums
#define SMEM_FLOATS (LP_OFF + TI*HH)           // 45408
#define SMEM_BYTES (SMEM_FLOATS * 4)           // 181632 (< 227 KB)

// ---------------- packed f32x2 helpers (FFMA2 on sm_103a) ----------------
__device__ __forceinline__ unsigned long long f2u(float2 a) {
    unsigned long long r;
    asm("mov.b64 %0, {%1, %2};" : "=l"(r) : "f"(a.x), "f"(a.y));
    return r;
}
__device__ __forceinline__ float2 u2f(unsigned long long a) {
    float2 r;
    asm("mov.b64 {%0, %1}, %2;" : "=f"(r.x), "=f"(r.y) : "l"(a));
    return r;
}
__device__ __forceinline__ float2 ffma2(float2 a, float2 b, float2 c) {
    unsigned long long r;
    asm("fma.rn.f32x2 %0, %1, %2, %3;"
        : "=l"(r) : "l"(f2u(a)), "l"(f2u(b)), "l"(f2u(c)));
    return u2f(r);
}
__device__ __forceinline__ float2 lo2(float4 v) { return make_float2(v.x, v.y); }
__device__ __forceinline__ float2 hi2(float4 v) { return make_float2(v.z, v.w); }

// Reduce 8 per-lane values r[0..7] across the 8 dd-lanes; lane dd -> sum of r[dd].
__device__ __forceinline__ float butterfly8(const float r[8],
                                            bool b0, bool b1, bool b2) {
    float c0 = b2 ? r[4] : r[0];
    float c1 = b2 ? r[5] : r[1];
    float c2 = b2 ? r[6] : r[2];
    float c3 = b2 ? r[7] : r[3];
    float d0 = b2 ? r[0] : r[4];
    float d1 = b2 ? r[1] : r[5];
    float d2 = b2 ? r[2] : r[6];
    float d3 = b2 ? r[3] : r[7];
    c0 += __shfl_xor_sync(0xffffffffu, d0, 4);
    c1 += __shfl_xor_sync(0xffffffffu, d1, 4);
    c2 += __shfl_xor_sync(0xffffffffu, d2, 4);
    c3 += __shfl_xor_sync(0xffffffffu, d3, 4);
    float e0 = b1 ? c2 : c0;
    float e1 = b1 ? c3 : c1;
    float f0 = b1 ? c0 : c2;
    float f1 = b1 ? c1 : c3;
    e0 += __shfl_xor_sync(0xffffffffu, f0, 2);
    e1 += __shfl_xor_sync(0xffffffffu, f1, 2);
    float w = b0 ? e1 : e0;
    float o = b0 ? e0 : e1;
    w += __shfl_xor_sync(0xffffffffu, o, 1);
    return w;
}

// Reduce 4 per-lane values r[0..3] across 8 dd-lanes; EVERY lane ends with the
// full sum of r[dd&3].
__device__ __forceinline__ float butterfly4(const float r[4],
                                            bool b0, bool b1) {
    float k0 = b1 ? r[2] : r[0];
    float k1 = b1 ? r[3] : r[1];
    float o0 = b1 ? r[0] : r[2];
    float o1 = b1 ? r[1] : r[3];
    k0 += __shfl_xor_sync(0xffffffffu, o0, 2);
    k1 += __shfl_xor_sync(0xffffffffu, o1, 2);
    float kk = b0 ? k1 : k0;
    float oo = b0 ? k0 : k1;
    kk += __shfl_xor_sync(0xffffffffu, oo, 1);
    kk += __shfl_xor_sync(0xffffffffu, kk, 4);
    return kk;
}

__global__ __launch_bounds__(NT, 1)
void rel_attn_kernel(const float* __restrict__ q,
                     const float* __restrict__ k,
                     const float* __restrict__ v,
                     const float* __restrict__ rel,
                     const float* __restrict__ mask,
                     float* __restrict__ out) {
    extern __shared__ float sm[];
    float* s_s   = sm + S_OFF;     // [TI]{[HH][SROW]} content scores -> e
    float* red1  = sm + RED1_OFF;  // [2][TI*HH][DKK] p.v per-jhalf partials
    float* red2  = sm + RED2_OFF;  // [TI*HH][DKK]    p.rel full sums
    float* lpart = sm + LP_OFF;    // [TI*HH] row sums

    const int bid  = blockIdx.x;
    const int b    = bid >> 6;
    const int i0   = (bid & 63) * TI;
    const int tid  = threadIdx.x;
    const int warp = tid >> 5;
    const int lane = tid & 31;
    const int dd   = lane & 7;
    const int jj   = lane >> 3;
    const bool b0  = (dd & 1) != 0;
    const bool b1  = (dd & 2) != 0;
    const bool b2  = (dd & 4) != 0;

    const float2 z2 = make_float2(0.f, 0.f);

    // ===== Phase 1a: content scores s = (scale*q).k ; warp=(h, jhalf) =======
    {
        const int h  = warp & 7;
        const int jo = (warp >> 3) * (NN / 2);
        float4 qa[TI], qb[TI];
#pragma unroll
        for (int ti = 0; ti < TI; ti++) {
            const float* qp = q + ((size_t)(b * HH + h) * NN + (i0 + ti)) * DKK + dd * 8;
            float4 a = *(const float4*)qp;
            float4 c = *(const float4*)(qp + 4);
            a.x *= SCALE; a.y *= SCALE; a.z *= SCALE; a.w *= SCALE;
            c.x *= SCALE; c.y *= SCALE; c.z *= SCALE; c.w *= SCALE;
            qa[ti] = a; qb[ti] = c;
        }
        const float* kbase = k + ((size_t)(b * HH + h) * NN) * DKK + dd * 8;
        float4 ka = *(const float4*)(kbase + (size_t)(jo + jj) * DKK);
        float4 kb = *(const float4*)(kbase + (size_t)(jo + jj) * DKK + 4);
#pragma unroll 2
        for (int s = 0; s < NN / 8; s++) {
            const int j  = jo + s * 4 + jj;
            const int sn = (s < NN / 8 - 1) ? s + 1 : s;
            const int jn = jo + sn * 4 + jj;
            const float4 na = *(const float4*)(kbase + (size_t)jn * DKK);
            const float4 nb = *(const float4*)(kbase + (size_t)jn * DKK + 4);
            float r[TI];
#pragma unroll
            for (int ti = 0; ti < TI; ti++) {
                float2 a = ffma2(lo2(qa[ti]), lo2(ka), z2);
                a = ffma2(hi2(qa[ti]), hi2(ka), a);
                a = ffma2(lo2(qb[ti]), lo2(kb), a);
                a = ffma2(hi2(qb[ti]), hi2(kb), a);
                r[ti] = a.x + a.y;
            }
            const float w = butterfly8(r, b0, b1, b2);   // lane dd -> ti=dd
            s_s[dd * TIBLK + h * SROW + j] = w;          // conflict-free
            ka = na; kb = nb;
        }
    }
    __syncthreads();

    // ===== FUSED chunked phase: rel scores + exp (sub1), p.rel (sub2) =======
    // warp = (ti, hg): heads hg*4..hg*4+3, ALL j, in 128-col chunks.
    // sub1 reads rel from DRAM once; sub2 re-reads the SAME 8KB chunk while
    // it is still L2/L1-resident (gap = one 32-step subloop).
    {
        const int ti = warp & 7;
        const int hg = warp >> 3;
        const int hl = dd & 3;
        const int h  = hg * 4 + hl;

        float4 qa[4], qb[4];
#pragma unroll
        for (int t = 0; t < 4; t++) {
            const float* qp = q + ((size_t)(b * HH + hg * 4 + t) * NN + (i0 + ti)) * DKK + dd * 8;
            qa[t] = *(const float4*)qp;
            qb[t] = *(const float4*)(qp + 4);
        }
        float2 acc[4][4];
#pragma unroll
        for (int t = 0; t < 4; t++)
#pragma unroll
            for (int c = 0; c < 4; c++) acc[t][c] = z2;
        float lsum = 0.f;

        const float* rbase = rel + (((size_t)b * NN + (i0 + ti)) * NN) * DKK + dd * 8;
        const float* mrow  = mask + ((size_t)(b * HH + h) * NN + (i0 + ti)) * NN;
        float* srow = s_s + ti * TIBLK + h * SROW;
        const float* sb = s_s + ti * TIBLK + (hg * 4) * SROW;  // head-group base

        for (int c = 0; c < NN / JCH; c++) {
            const int j0 = c * JCH;

            // ---- sub1: scores + exp + e-store --------------------------------
            {
                float4 ra = __ldg((const float4*)(rbase + (size_t)(j0 + jj) * DKK));
                float4 rb = __ldg((const float4*)(rbase + (size_t)(j0 + jj) * DKK + 4));
#pragma unroll 2
                for (int s = 0; s < JCH / 4; s++) {
                    const int j  = j0 + s * 4 + jj;
                    const int sn = (s < JCH / 4 - 1) ? s + 1 : s;
                    const int jn = j0 + sn * 4 + jj;
                    const float4 na = __ldg((const float4*)(rbase + (size_t)jn * DKK));
                    const float4 nb = __ldg((const float4*)(rbase + (size_t)jn * DKK + 4));
                    const float mval = mrow[j];
                    const float cval = srow[j];
                    float r[4];
#pragma unroll
                    for (int t = 0; t < 4; t++) {
                        float2 a = ffma2(lo2(qa[t]), lo2(ra), z2);
                        a = ffma2(hi2(qa[t]), hi2(ra), a);
                        a = ffma2(lo2(qb[t]), lo2(rb), a);
                        a = ffma2(hi2(qb[t]), hi2(rb), a);
                        r[t] = a.x + a.y;
                    }
                    const float w = butterfly4(r, b0, b1);   // all lanes: h=hl
                    const float e = __expf(w + cval + mval);
                    if (dd < 4) srow[j] = e;
                    lsum += e;
                    ra = na; rb = nb;
                }
            }
            __syncwarp();

            // ---- sub2: p.rel accumulate (rel re-read is L2/L1-hot) -----------
            {
                float4 ra = __ldcs((const float4*)(rbase + (size_t)(j0 + jj) * DKK));
                float4 rb = __ldcs((const float4*)(rbase + (size_t)(j0 + jj) * DKK + 4));
#pragma unroll 2
                for (int s = 0; s < JCH / 4; s++) {
                    const int j  = j0 + s * 4 + jj;
                    const int sn = (s < JCH / 4 - 1) ? s + 1 : s;
                    const int jn = j0 + sn * 4 + jj;
                    const float4 na = __ldcs((const float4*)(rbase + (size_t)jn * DKK));
                    const float4 nb = __ldcs((const float4*)(rbase + (size_t)jn * DKK + 4));
#pragma unroll
                    for (int t = 0; t < 4; t++) {
                        const float e = sb[t * SROW + j];
                        const float2 e2 = make_float2(e, e);
                        acc[t][0] = ffma2(e2, lo2(ra), acc[t][0]);
                        acc[t][1] = ffma2(e2, hi2(ra), acc[t][1]);
                        acc[t][2] = ffma2(e2, lo2(rb), acc[t][2]);
                        acc[t][3] = ffma2(e2, hi2(rb), acc[t][3]);
                    }
                    ra = na; rb = nb;
                }
            }
            // next sub1 writes different j-columns; no sync needed
        }

        // row sums: lanes dd and dd^4 hold IDENTICAL sums (same hl, same jj);
        // reduce ONLY over the jj bits (xor 8, 16), write from lane<4.
        lsum += __shfl_xor_sync(0xffffffffu, lsum, 8);
        lsum += __shfl_xor_sync(0xffffffffu, lsum, 16);
        if (lane < 4) lpart[ti * HH + hg * 4 + hl] = lsum;

        // reduce acc over jj groups, write p.rel sums
#pragma unroll
        for (int t = 0; t < 4; t++)
#pragma unroll
            for (int c = 0; c < 4; c++) {
                acc[t][c].x += __shfl_xor_sync(0xffffffffu, acc[t][c].x, 8);
                acc[t][c].x += __shfl_xor_sync(0xffffffffu, acc[t][c].x, 16);
                acc[t][c].y += __shfl_xor_sync(0xffffffffu, acc[t][c].y, 8);
                acc[t][c].y += __shfl_xor_sync(0xffffffffu, acc[t][c].y, 16);
            }
        if (jj == 0) {
#pragma unroll
            for (int t = 0; t < 4; t++) {
                float* rp = red2 + (ti * HH + hg * 4 + t) * DKK + dd * 8;
                *(float4*)rp       = make_float4(acc[t][0].x, acc[t][0].y,
                                                 acc[t][1].x, acc[t][1].y);
                *(float4*)(rp + 4) = make_float4(acc[t][2].x, acc[t][2].y,
                                                 acc[t][3].x, acc[t][3].y);
            }
        }
    }
    __syncthreads();

    // ===== Phase 2a: out1 = p.v ; warp=(h, jhalf) ===========================
    {
        const int h  = warp & 7;
        const int jh = warp >> 3;
        const int jo = jh * (NN / 2);
        float2 acc[TI][4];
#pragma unroll
        for (int ti = 0; ti < TI; ti++)
#pragma unroll
            for (int c = 0; c < 4; c++) acc[ti][c] = z2;

        const float* vbase = v + ((size_t)(b * HH + h) * NN) * DKK + dd * 8;
        float4 va = *(const float4*)(vbase + (size_t)(jo + jj) * DKK);
        float4 vb = *(const float4*)(vbase + (size_t)(jo + jj) * DKK + 4);
#pragma unroll 2
        for (int s = 0; s < NN / 8; s++) {
            const int j  = jo + s * 4 + jj;
            const int sn = (s < NN / 8 - 1) ? s + 1 : s;
            const int jn = jo + sn * 4 + jj;
            const float4 na = *(const float4*)(vbase + (size_t)jn * DKK);
            const float4 nb = *(const float4*)(vbase + (size_t)jn * DKK + 4);
#pragma unroll
            for (int ti = 0; ti < TI; ti++) {
                const float e = s_s[ti * TIBLK + h * SROW + j];
                const float2 e2 = make_float2(e, e);
                acc[ti][0] = ffma2(e2, lo2(va), acc[ti][0]);
                acc[ti][1] = ffma2(e2, hi2(va), acc[ti][1]);
                acc[ti][2] = ffma2(e2, lo2(vb), acc[ti][2]);
                acc[ti][3] = ffma2(e2, hi2(vb), acc[ti][3]);
            }
            va = na; vb = nb;
        }
#pragma unroll
        for (int ti = 0; ti < TI; ti++)
#pragma unroll
            for (int c = 0; c < 4; c++) {
                acc[ti][c].x += __shfl_xor_sync(0xffffffffu, acc[ti][c].x, 8);
                acc[ti][c].x += __shfl_xor_sync(0xffffffffu, acc[ti][c].x, 16);
                acc[ti][c].y += __shfl_xor_sync(0xffffffffu, acc[ti][c].y, 8);
                acc[ti][c].y += __shfl_xor_sync(0xffffffffu, acc[ti][c].y, 16);
            }
        if (jj == 0) {
#pragma unroll
            for (int ti = 0; ti < TI; ti++) {
                float* rp = red1 + ((size_t)jh * TI * HH * DKK) +
                            (ti * HH + h) * DKK + dd * 8;
                *(float4*)rp       = make_float4(acc[ti][0].x, acc[ti][0].y,
                                                 acc[ti][1].x, acc[ti][1].y);
                *(float4*)(rp + 4) = make_float4(acc[ti][2].x, acc[ti][2].y,
                                                 acc[ti][3].x, acc[ti][3].y);
            }
        }
    }
    __syncthreads();

    // ===== Combine + normalize + store (float4) =============================
    {
        const int Q = TI * HH * DKK / 4;            // 1024 float4s
        const float4* r14 = (const float4*)red1;
        const float4* r24 = (const float4*)red2;
#pragma unroll
        for (int it = 0; it < 2; it++) {
            const int idx4 = it * NT + tid;
            const float4 a0 = r14[idx4];
            const float4 a1 = r14[Q + idx4];
            const float4 c0 = r24[idx4];
            const int row = idx4 >> 4;               // ti*8+h
            const int ti  = row >> 3;
            const int h   = row & 7;
            const int d   = (idx4 & 15) << 2;
            const float s = 1.0f / lpart[row];
            float4 o;
            o.x = ((a0.x + a1.x) + c0.x) * s;
            o.y = ((a0.y + a1.y) + c0.y) * s;
            o.z = ((a0.z + a1.z) + c0.z) * s;
            o.w = ((a0.w + a1.w) + c0.w) * s;
            *(float4*)&out[((size_t)(b * HH + h) * NN + (i0 + ti)) * DKK + d] = o;
        }
    }
}

extern "C" void kernel_launch(void* const* d_in, const int* in_sizes, int n_in,
                              void* d_out, int out_size) {
    const float* q    = (const float*)d_in[0];
    const float* k    = (const float*)d_in[1];
    const float* v    = (const float*)d_in[2];
    const float* rel  = (const float*)d_in[3];
    const float* mask = (const float*)d_in[4];
    float* out = (float*)d_out;

    cudaFuncSetAttribute(rel_attn_kernel,
                         cudaFuncAttributeMaxDynamicSharedMemorySize, SMEM_BYTES);
    rel_attn_kernel<<<BB * (NN / TI), NT, SMEM_BYTES>>>(q, k, v, rel, mask, out);
}

// round 14
// speedup vs baseline: 1.2880x; 1.2499x over previous
#include <cuda_runtime.h>
#include <cuda_bf16.h>
#include <math.h>

// Shapes fixed for this bench: B=4, H=8, N=512, DK=64
#define BB 4
#define HH 8
#define NN 512
#define DKK 64
#define TI 8                 // i-rows per CTA
#define NT 512               // threads per CTA (16 warps)
#define SCALE 0.125f         // 1/sqrt(64)
#define SROW 516             // padded score row (stride mod 32 = 4)
#define TIBLK (HH*SROW + 4)  // 4132 (stride mod 32 = 4)

// smem layout in floats
#define S_OFF    0
#define RED1_OFF (TI*TIBLK)                    // 33056 ; [2][TI*HH][DKK] p.v
#define RED2_OFF (RED1_OFF + 2*TI*HH*DKK)      // 41248 ; [2][TI*HH][DKK] p.rel
#define LP_OFF   (RED2_OFF + 2*TI*HH*DKK)      // 49440 ; [2][TI*HH] row sums
#define SMEM_FLOATS (LP_OFF + 2*TI*HH)         // 49568
#define SMEM_BYTES (SMEM_FLOATS * 4)           // 198272 (< 227 KB)

// ---------------- packed f32x2 helpers (FFMA2 on sm_103a) ----------------
__device__ __forceinline__ unsigned long long f2u(float2 a) {
    unsigned long long r;
    asm("mov.b64 %0, {%1, %2};" : "=l"(r) : "f"(a.x), "f"(a.y));
    return r;
}
__device__ __forceinline__ float2 u2f(unsigned long long a) {
    float2 r;
    asm("mov.b64 {%0, %1}, %2;" : "=f"(r.x), "=f"(r.y) : "l"(a));
    return r;
}
__device__ __forceinline__ float2 ffma2(float2 a, float2 b, float2 c) {
    unsigned long long r;
    asm("fma.rn.f32x2 %0, %1, %2, %3;"
        : "=l"(r) : "l"(f2u(a)), "l"(f2u(b)), "l"(f2u(c)));
    return u2f(r);
}
__device__ __forceinline__ float2 lo2(float4 v) { return make_float2(v.x, v.y); }
__device__ __forceinline__ float2 hi2(float4 v) { return make_float2(v.z, v.w); }

// Reduce 8 per-lane values r[0..7] across the 8 dd-lanes; lane dd -> sum of r[dd].
__device__ __forceinline__ float butterfly8(const float r[8],
                                            bool b0, bool b1, bool b2) {
    float c0 = b2 ? r[4] : r[0];
    float c1 = b2 ? r[5] : r[1];
    float c2 = b2 ? r[6] : r[2];
    float c3 = b2 ? r[7] : r[3];
    float d0 = b2 ? r[0] : r[4];
    float d1 = b2 ? r[1] : r[5];
    float d2 = b2 ? r[2] : r[6];
    float d3 = b2 ? r[3] : r[7];
    c0 += __shfl_xor_sync(0xffffffffu, d0, 4);
    c1 += __shfl_xor_sync(0xffffffffu, d1, 4);
    c2 += __shfl_xor_sync(0xffffffffu, d2, 4);
    c3 += __shfl_xor_sync(0xffffffffu, d3, 4);
    float e0 = b1 ? c2 : c0;
    float e1 = b1 ? c3 : c1;
    float f0 = b1 ? c0 : c2;
    float f1 = b1 ? c1 : c3;
    e0 += __shfl_xor_sync(0xffffffffu, f0, 2);
    e1 += __shfl_xor_sync(0xffffffffu, f1, 2);
    float w = b0 ? e1 : e0;
    float o = b0 ? e0 : e1;
    w += __shfl_xor_sync(0xffffffffu, o, 1);
    return w;
}

__global__ __launch_bounds__(NT, 1)
void rel_attn_kernel(const float* __restrict__ q,
                     const float* __restrict__ k,
                     const float* __restrict__ v,
                     const float* __restrict__ rel,
                     const float* __restrict__ mask,
                     float* __restrict__ out) {
    extern __shared__ float sm[];
    float* s_s   = sm + S_OFF;     // [TI]{[HH][SROW]} scores(+mask) -> e
    float* red1  = sm + RED1_OFF;  // [2][TI*HH][DKK] p.v per-jhalf partials
    float* red2  = sm + RED2_OFF;  // [2][TI*HH][DKK] p.rel per-jhalf partials
    float* lpart = sm + LP_OFF;    // [2][TI*HH] row-sum partials

    const int bid  = blockIdx.x;
    const int b    = bid >> 6;
    const int i0   = (bid & 63) * TI;
    const int tid  = threadIdx.x;
    const int warp = tid >> 5;
    const int lane = tid & 31;
    const int dd   = lane & 7;
    const int jj   = lane >> 3;
    const bool b0  = (dd & 1) != 0;
    const bool b1  = (dd & 2) != 0;
    const bool b2  = (dd & 4) != 0;

    const int sub  = warp & 7;           // head (1a/2a) or ti (1b/2b)
    const int jh   = warp >> 3;          // j-half owned by this warp
    const int jo   = jh * (NN / 2);

    const float2 z2 = make_float2(0.f, 0.f);

    // ===== Phase 1a: s = (scale*q).k + mask ; warp=(h, jhalf) ===============
    {
        const int h = sub;
        float4 qa[TI], qb[TI];
#pragma unroll
        for (int ti = 0; ti < TI; ti++) {
            const float* qp = q + ((size_t)(b * HH + h) * NN + (i0 + ti)) * DKK + dd * 8;
            float4 a = *(const float4*)qp;
            float4 c = *(const float4*)(qp + 4);
            a.x *= SCALE; a.y *= SCALE; a.z *= SCALE; a.w *= SCALE;
            c.x *= SCALE; c.y *= SCALE; c.z *= SCALE; c.w *= SCALE;
            qa[ti] = a; qb[ti] = c;
        }
        const float* kbase = k + ((size_t)(b * HH + h) * NN) * DKK + dd * 8;
        float4 ka = *(const float4*)(kbase + (size_t)(jo + jj) * DKK);
        float4 kb = *(const float4*)(kbase + (size_t)(jo + jj) * DKK + 4);
#pragma unroll 2
        for (int s = 0; s < NN / 8; s++) {
            const int j  = jo + s * 4 + jj;
            const int sn = (s < NN / 8 - 1) ? s + 1 : s;
            const int jn = jo + sn * 4 + jj;
            const float4 na = *(const float4*)(kbase + (size_t)jn * DKK);
            const float4 nb = *(const float4*)(kbase + (size_t)jn * DKK + 4);
            float r[TI];
#pragma unroll
            for (int ti = 0; ti < TI; ti++) {
                float2 a = ffma2(lo2(qa[ti]), lo2(ka), z2);
                a = ffma2(hi2(qa[ti]), hi2(ka), a);
                a = ffma2(lo2(qb[ti]), lo2(kb), a);
                a = ffma2(hi2(qb[ti]), hi2(kb), a);
                r[ti] = a.x + a.y;
            }
            const float w = butterfly8(r, b0, b1, b2);   // lane dd -> ti=dd
            s_s[dd * TIBLK + h * SROW + j] = w;          // conflict-free
            ka = na; kb = nb;
        }

        // --- mask epilogue: s_s rows (all ti, h, j in jhalf) += mask --------
        // This warp wrote exactly those rows above; fully coalesced float4.
#pragma unroll
        for (int ti = 0; ti < TI; ti++) {
            const float4* mp4 = (const float4*)(mask +
                ((size_t)(b * HH + h) * NN + (i0 + ti)) * NN + jo);
            float4* sr4 = (float4*)(s_s + ti * TIBLK + h * SROW + jo);
#pragma unroll
            for (int t = 0; t < 2; t++) {
                const int x = t * 32 + lane;             // 64 float4 per row-half
                float4 sv = sr4[x];
                const float4 mv = mp4[x];
                sv.x += mv.x; sv.y += mv.y; sv.z += mv.z; sv.w += mv.w;
                sr4[x] = sv;
            }
        }
    }
    __syncthreads();

    // ===== Phase 1b: e = exp(q.rel + s_s) ; warp=(ti, jhalf) ================
    {
        const int ti = sub;
        float4 qa[HH], qb[HH];
#pragma unroll
        for (int h = 0; h < HH; h++) {
            const float* qp = q + ((size_t)(b * HH + h) * NN + (i0 + ti)) * DKK + dd * 8;
            qa[h] = *(const float4*)qp;
            qb[h] = *(const float4*)(qp + 4);
        }
        const float* rbase = rel + (((size_t)b * NN + (i0 + ti)) * NN) * DKK + dd * 8;
        float* srow = s_s + ti * TIBLK + dd * SROW;
        float lsum = 0.f;

        float4 ra = __ldg((const float4*)(rbase + (size_t)(jo + jj) * DKK));
        float4 rb = __ldg((const float4*)(rbase + (size_t)(jo + jj) * DKK + 4));
#pragma unroll 2
        for (int s = 0; s < NN / 8; s++) {
            const int j  = jo + s * 4 + jj;
            const int sn = (s < NN / 8 - 1) ? s + 1 : s;
            const int jn = jo + sn * 4 + jj;
            const float4 na = __ldg((const float4*)(rbase + (size_t)jn * DKK));
            const float4 nb = __ldg((const float4*)(rbase + (size_t)jn * DKK + 4));
            float r[HH];
#pragma unroll
            for (int h = 0; h < HH; h++) {
                float2 a = ffma2(lo2(qa[h]), lo2(ra), z2);
                a = ffma2(hi2(qa[h]), hi2(ra), a);
                a = ffma2(lo2(qb[h]), lo2(rb), a);
                a = ffma2(hi2(qb[h]), hi2(rb), a);
                r[h] = a.x + a.y;
            }
            const float w = butterfly8(r, b0, b1, b2);   // lane dd -> h=dd
            const float e = __expf(w + srow[j]);         // content+mask in s_s
            srow[j] = e;                                 // conflict-free RMW
            lsum += e;
            ra = na; rb = nb;
        }
        // row-sum partial: reduce over the 4 jj lanes for fixed dd
        lsum += __shfl_xor_sync(0xffffffffu, lsum, 8);
        lsum += __shfl_xor_sync(0xffffffffu, lsum, 16);
        if (jj == 0) lpart[jh * (TI * HH) + ti * HH + dd] = lsum;
    }
    __syncthreads();

    // ===== Phases 2a / 2b (order alternates by CTA parity) ==================
    // 2b (p.rel) immediately after 1b keeps the CTA's rel tile L2-resident;
    // alternating halves the instantaneous rel footprint across the chip so
    // the "immediate" CTAs actually fit in L2.

    auto phase2b = [&]() {   // out2 = p.rel ; warp=(ti, jhalf), j DESCENDING
        const int ti = sub;
        float2 acc[HH][4];
#pragma unroll
        for (int h = 0; h < HH; h++)
#pragma unroll
            for (int c = 0; c < 4; c++) acc[h][c] = z2;

        const float* rbase = rel + (((size_t)b * NN + (i0 + ti)) * NN) * DKK + dd * 8;
        const int jstart = jo + (NN / 8 - 1) * 4 + jj;
        float4 ra = __ldcs((const float4*)(rbase + (size_t)jstart * DKK));
        float4 rb = __ldcs((const float4*)(rbase + (size_t)jstart * DKK + 4));
#pragma unroll 2
        for (int s = NN / 8 - 1; s >= 0; s--) {
            const int j  = jo + s * 4 + jj;
            const int sn = (s > 0) ? s - 1 : 0;
            const int jn = jo + sn * 4 + jj;
            const float4 na = __ldcs((const float4*)(rbase + (size_t)jn * DKK));
            const float4 nb = __ldcs((const float4*)(rbase + (size_t)jn * DKK + 4));
#pragma unroll
            for (int h = 0; h < HH; h++) {
                const float e = s_s[ti * TIBLK + h * SROW + j];
                const float2 e2 = make_float2(e, e);
                acc[h][0] = ffma2(e2, lo2(ra), acc[h][0]);
                acc[h][1] = ffma2(e2, hi2(ra), acc[h][1]);
                acc[h][2] = ffma2(e2, lo2(rb), acc[h][2]);
                acc[h][3] = ffma2(e2, hi2(rb), acc[h][3]);
            }
            ra = na; rb = nb;
        }
#pragma unroll
        for (int h = 0; h < HH; h++)
#pragma unroll
            for (int c = 0; c < 4; c++) {
                acc[h][c].x += __shfl_xor_sync(0xffffffffu, acc[h][c].x, 8);
                acc[h][c].x += __shfl_xor_sync(0xffffffffu, acc[h][c].x, 16);
                acc[h][c].y += __shfl_xor_sync(0xffffffffu, acc[h][c].y, 8);
                acc[h][c].y += __shfl_xor_sync(0xffffffffu, acc[h][c].y, 16);
            }
        if (jj == 0) {
#pragma unroll
            for (int h = 0; h < HH; h++) {
                float* rp = red2 + ((size_t)jh * TI * HH * DKK) +
                            (ti * HH + h) * DKK + dd * 8;
                *(float4*)rp       = make_float4(acc[h][0].x, acc[h][0].y,
                                                 acc[h][1].x, acc[h][1].y);
                *(float4*)(rp + 4) = make_float4(acc[h][2].x, acc[h][2].y,
                                                 acc[h][3].x, acc[h][3].y);
            }
        }
    };

    auto phase2a = [&]() {   // out1 = p.v ; warp=(h, jhalf)
        const int h = sub;
        float2 acc[TI][4];
#pragma unroll
        for (int ti = 0; ti < TI; ti++)
#pragma unroll
            for (int c = 0; c < 4; c++) acc[ti][c] = z2;

        const float* vbase = v + ((size_t)(b * HH + h) * NN) * DKK + dd * 8;
        float4 va = *(const float4*)(vbase + (size_t)(jo + jj) * DKK);
        float4 vb = *(const float4*)(vbase + (size_t)(jo + jj) * DKK + 4);
#pragma unroll 2
        for (int s = 0; s < NN / 8; s++) {
            const int j  = jo + s * 4 + jj;
            const int sn = (s < NN / 8 - 1) ? s + 1 : s;
            const int jn = jo + sn * 4 + jj;
            const float4 na = *(const float4*)(vbase + (size_t)jn * DKK);
            const float4 nb = *(const float4*)(vbase + (size_t)jn * DKK + 4);
#pragma unroll
            for (int ti = 0; ti < TI; ti++) {
                const float e = s_s[ti * TIBLK + h * SROW + j];
                const float2 e2 = make_float2(e, e);
                acc[ti][0] = ffma2(e2, lo2(va), acc[ti][0]);
                acc[ti][1] = ffma2(e2, hi2(va), acc[ti][1]);
                acc[ti][2] = ffma2(e2, lo2(vb), acc[ti][2]);
                acc[ti][3] = ffma2(e2, hi2(vb), acc[ti][3]);
            }
            va = na; vb = nb;
        }
#pragma unroll
        for (int ti = 0; ti < TI; ti++)
#pragma unroll
            for (int c = 0; c < 4; c++) {
                acc[ti][c].x += __shfl_xor_sync(0xffffffffu, acc[ti][c].x, 8);
                acc[ti][c].x += __shfl_xor_sync(0xffffffffu, acc[ti][c].x, 16);
                acc[ti][c].y += __shfl_xor_sync(0xffffffffu, acc[ti][c].y, 8);
                acc[ti][c].y += __shfl_xor_sync(0xffffffffu, acc[ti][c].y, 16);
            }
        if (jj == 0) {
#pragma unroll
            for (int ti = 0; ti < TI; ti++) {
                float* rp = red1 + ((size_t)jh * TI * HH * DKK) +
                            (ti * HH + h) * DKK + dd * 8;
                *(float4*)rp       = make_float4(acc[ti][0].x, acc[ti][0].y,
                                                 acc[ti][1].x, acc[ti][1].y);
                *(float4*)(rp + 4) = make_float4(acc[ti][2].x, acc[ti][2].y,
                                                 acc[ti][3].x, acc[ti][3].y);
            }
        }
    };

    if ((bid & 1) == 0) { phase2b(); phase2a(); }
    else                { phase2a(); phase2b(); }
    __syncthreads();

    // ===== Combine + normalize + store (float4) =============================
    {
        const int Q = TI * HH * DKK / 4;            // 1024 float4s
        const float4* r14 = (const float4*)red1;
        const float4* r24 = (const float4*)red2;
#pragma unroll
        for (int it = 0; it < 2; it++) {
            const int idx4 = it * NT + tid;
            const float4 a0 = r14[idx4];
            const float4 a1 = r14[Q + idx4];
            const float4 c0 = r24[idx4];
            const float4 c1 = r24[Q + idx4];
            const int row = idx4 >> 4;               // ti*8+h
            const int ti  = row >> 3;
            const int h   = row & 7;
            const int d   = (idx4 & 15) << 2;
            const float s = 1.0f / (lpart[row] + lpart[TI * HH + row]);
            float4 o;
            o.x = ((a0.x + a1.x) + (c0.x + c1.x)) * s;
            o.y = ((a0.y + a1.y) + (c0.y + c1.y)) * s;
            o.z = ((a0.z + a1.z) + (c0.z + c1.z)) * s;
            o.w = ((a0.w + a1.w) + (c0.w + c1.w)) * s;
            *(float4*)&out[((size_t)(b * HH + h) * NN + (i0 + ti)) * DKK + d] = o;
        }
    }
}

extern "C" void kernel_launch(void* const* d_in, const int* in_sizes, int n_in,
                              void* d_out, int out_size) {
    const float* q    = (const float*)d_in[0];
    const float* k    = (const float*)d_in[1];
    const float* v    = (const float*)d_in[2];
    const float* rel  = (const float*)d_in[3];
    const float* mask = (const float*)d_in[4];
    float* out = (float*)d_out;

    cudaFuncSetAttribute(rel_attn_kernel,
                         cudaFuncAttributeMaxDynamicSharedMemorySize, SMEM_BYTES);
    rel_attn_kernel<<<BB * (NN / TI), NT, SMEM_BYTES>>>(q, k, v, rel, mask, out);
}